// round 9
// baseline (speedup 1.0000x reference)
#include <cuda_runtime.h>
#include <cuda_fp16.h>
#include <math.h>
#include <stdint.h>

#define TTOK 2048
#define HDIM 2048
#define IDIM 1024
#define ENUM 64
#define KTOP 8

// Scratch (static device globals; no dynamic allocation allowed)
__device__ int   g_cnt[ENUM];
__device__ int   g_off[ENUM];
__device__ int   g_tok[ENUM * TTOK];
__device__ float g_wt[ENUM * TTOK];
__device__ __half g_x_h[(size_t)TTOK * HDIM];
__device__ __half g_wg_h[(size_t)ENUM * HDIM * IDIM];
__device__ __half g_wu_h[(size_t)ENUM * HDIM * IDIM];
__device__ __half g_wd_h[(size_t)ENUM * IDIM * HDIM];
__device__ __half g_h[(size_t)TTOK * KTOP * IDIM];

// ---------------------------------------------------------------------------
// helpers
// ---------------------------------------------------------------------------
__device__ __forceinline__ uint32_t cvsm(const void* p) {
    return (uint32_t)__cvta_generic_to_shared(p);
}
__device__ __forceinline__ void ldsm4(uint32_t* r, uint32_t a) {
    asm volatile("ldmatrix.sync.aligned.m8n8.x4.shared.b16 {%0,%1,%2,%3},[%4];"
                 : "=r"(r[0]), "=r"(r[1]), "=r"(r[2]), "=r"(r[3]) : "r"(a));
}
__device__ __forceinline__ void ldsm4t(uint32_t& r0, uint32_t& r1, uint32_t& r2, uint32_t& r3, uint32_t a) {
    asm volatile("ldmatrix.sync.aligned.m8n8.x4.trans.shared.b16 {%0,%1,%2,%3},[%4];"
                 : "=r"(r0), "=r"(r1), "=r"(r2), "=r"(r3) : "r"(a));
}
__device__ __forceinline__ void mma16816(float* c, const uint32_t* a, const uint32_t* b) {
    asm volatile("mma.sync.aligned.m16n8k16.row.col.f32.f16.f16.f32 "
                 "{%0,%1,%2,%3},{%4,%5,%6,%7},{%8,%9},{%0,%1,%2,%3};"
                 : "+f"(c[0]), "+f"(c[1]), "+f"(c[2]), "+f"(c[3])
                 : "r"(a[0]), "r"(a[1]), "r"(a[2]), "r"(a[3]), "r"(b[0]), "r"(b[1]));
}
__device__ __forceinline__ uint32_t packh2(float a, float b) {
    __half2 h = __floats2half2_rn(a, b);
    return *(uint32_t*)&h;
}
__device__ __forceinline__ void cpa16(uint32_t s, const void* g) {
    asm volatile("cp.async.cg.shared.global [%0], [%1], 16;" :: "r"(s), "l"(g));
}
__device__ __forceinline__ void cpa_commit() {
    asm volatile("cp.async.commit_group;");
}
__device__ __forceinline__ void cpa_wait1() {
    asm volatile("cp.async.wait_group 1;");
}
__device__ __forceinline__ void cpa_wait0() {
    asm volatile("cp.async.wait_group 0;");
}
__device__ __forceinline__ void red2(float* p, float a, float b) {
    asm volatile("red.global.add.v2.f32 [%0], {%1,%2};" :: "l"(p), "f"(a), "f"(b) : "memory");
}

// ---------------------------------------------------------------------------
// K-split: all three weight tensors fp32 -> fp16 in one launch (grid.y = tensor)
// ---------------------------------------------------------------------------
__global__ void splitw_kernel(const float4* __restrict__ wg,
                              const float4* __restrict__ wu,
                              const float4* __restrict__ wd) {
    const size_t n4 = (size_t)ENUM * HDIM * IDIM / 4;
    const float4* src;
    uint2* dst;
    if (blockIdx.y == 0)      { src = wg; dst = (uint2*)g_wg_h; }
    else if (blockIdx.y == 1) { src = wu; dst = (uint2*)g_wu_h; }
    else                      { src = wd; dst = (uint2*)g_wd_h; }
    size_t idx = (size_t)blockIdx.x * blockDim.x + threadIdx.x;
    size_t stride = (size_t)gridDim.x * blockDim.x;
    for (size_t i = idx; i < n4; i += stride) {
        float4 v = src[i];
        dst[i] = make_uint2(packh2(v.x, v.y), packh2(v.z, v.w));
    }
}

// ---------------------------------------------------------------------------
// K0: zero output accumulation region + reset counters
// ---------------------------------------------------------------------------
__global__ void zero_kernel(float* __restrict__ out) {
    size_t idx = (size_t)blockIdx.x * blockDim.x + threadIdx.x;
    size_t n4 = (size_t)TTOK * HDIM / 4;
    float4 z = make_float4(0.f, 0.f, 0.f, 0.f);
    for (size_t i = idx; i < n4; i += (size_t)gridDim.x * blockDim.x)
        reinterpret_cast<float4*>(out)[i] = z;
    if (blockIdx.x == 0 && threadIdx.x < ENUM) g_cnt[threadIdx.x] = 0;
}

// ---------------------------------------------------------------------------
// K1: router (also emits fp16 copy of x)
// ---------------------------------------------------------------------------
__global__ void router_kernel(const float* __restrict__ x,
                              const float* __restrict__ gw,
                              float* __restrict__ out) {
    int t = blockIdx.x;
    __shared__ float xs[HDIM];
    __shared__ float logits[ENUM];
    __shared__ float probs[ENUM];

    const float* xr = x + (size_t)t * HDIM;
    for (int i = threadIdx.x; i < HDIM; i += blockDim.x) xs[i] = xr[i];
    __syncthreads();

    // fp16 copy of this token's row
    for (int i = threadIdx.x; i < HDIM / 2; i += blockDim.x) {
        *(uint32_t*)&g_x_h[(size_t)t * HDIM + 2 * i] = packh2(xs[2 * i], xs[2 * i + 1]);
    }

    int e = threadIdx.x >> 2;
    int part = threadIdx.x & 3;
    float s = 0.f;
    int k0 = part * (HDIM / 4);
    for (int k = k0; k < k0 + HDIM / 4; k++)
        s += xs[k] * gw[(size_t)k * ENUM + e];
    s += __shfl_down_sync(0xffffffffu, s, 2);
    s += __shfl_down_sync(0xffffffffu, s, 1);
    if (part == 0) logits[e] = s;
    __syncthreads();

    if (threadIdx.x < ENUM)
        out[(size_t)TTOK * HDIM + (size_t)t * ENUM + threadIdx.x] = logits[threadIdx.x];

    if (threadIdx.x == 0) {
        float m = -1e30f;
        for (int i = 0; i < ENUM; i++) m = fmaxf(m, logits[i]);
        float sum = 0.f;
        for (int i = 0; i < ENUM; i++) { probs[i] = expf(logits[i] - m); sum += probs[i]; }
        float inv = 1.f / sum;
        for (int k = 0; k < KTOP; k++) {
            int best = 0; float bv = -1.f;
            for (int i = 0; i < ENUM; i++)
                if (probs[i] > bv) { bv = probs[i]; best = i; }
            probs[best] = -2.f;
            int pos = atomicAdd(&g_cnt[best], 1);
            g_tok[best * TTOK + pos] = t;
            g_wt[best * TTOK + pos]  = bv * inv;
        }
    }
}

// ---------------------------------------------------------------------------
// K2: prefix sum
// ---------------------------------------------------------------------------
__global__ void scan_kernel() {
    if (threadIdx.x == 0) {
        int acc = 0;
        for (int e = 0; e < ENUM; e++) { g_off[e] = acc; acc += g_cnt[e]; }
    }
}

// ---------------------------------------------------------------------------
// K3: gateup fp16. 512 thr, 16 warps: 0-7 gate / 8-15 up, warptile m32n64.
//     CTA tile M=256, N=64 per matrix, BK=32, 3-stage cp.async.
// ---------------------------------------------------------------------------
#define GU_ITERS 64
#define GU_A  0
#define GU_G  20480
#define GU_U  25088
#define GU_STG 29696
#define GU_SMEM (3 * GU_STG)

__global__ __launch_bounds__(512, 1)
void gateup_f16(float* __restrict__ dummy) {
    int e = blockIdx.z;
    int cnt = g_cnt[e];
    int mblk = blockIdx.y * 256;
    if (mblk >= cnt) return;
    int nblk = blockIdx.x * 64;

    extern __shared__ char smem[];
    uint32_t smb = cvsm(smem);

    const int tid = threadIdx.x;
    const int lane = tid & 31, wid = tid >> 5;
    const int wm = wid & 7;
    const bool isup = wid >= 8;

    // A loader: 1024 chunks of 16B (256 rows x 4 chunks), 2 per thread
    int ac1 = tid, ac2 = tid + 512;
    int ar1 = ac1 >> 2, aq1 = ac1 & 3;
    int ar2 = ac2 >> 2, aq2 = ac2 & 3;
    int mr1 = min(mblk + ar1, cnt - 1);
    int mr2 = min(mblk + ar2, cnt - 1);
    const __half* ap1 = g_x_h + (size_t)g_tok[e * TTOK + mr1] * HDIM + aq1 * 8;
    const __half* ap2 = g_x_h + (size_t)g_tok[e * TTOK + mr2] * HDIM + aq2 * 8;
    const uint32_t sA1 = GU_A + ar1 * 80 + aq1 * 16;
    const uint32_t sA2 = GU_A + ar2 * 80 + aq2 * 16;

    // B loader: gate+up, each 32 rows x 8 chunks = 512 total, 1 per thread
    size_t we = (size_t)e * HDIM * IDIM;
    int t1 = tid >> 8, kr1 = (tid >> 3) & 31, q1 = tid & 7;
    const __half* bp1 = (t1 ? g_wu_h : g_wg_h) + we + (size_t)kr1 * IDIM + nblk + q1 * 8;
    const uint32_t sB1 = (t1 ? GU_U : GU_G) + kr1 * 144 + q1 * 16;

    auto issue = [&](int st, int kb) {
        uint32_t sb = smb + st * GU_STG;
        cpa16(sb + sA1, ap1 + kb);
        cpa16(sb + sA2, ap2 + kb);
        cpa16(sb + sB1, bp1 + (size_t)kb * IDIM);
    };

    float acc[2][8][4] = {};
    const uint32_t bOff = isup ? GU_U : GU_G;

    issue(0, 0);  cpa_commit();
    issue(1, 32); cpa_commit();

    for (int it = 0; it < GU_ITERS; ++it) {
        int s = it % 3;
        cpa_wait1();
        __syncthreads();
        if (it + 2 < GU_ITERS) issue((it + 2) % 3, (it + 2) * 32);
        cpa_commit();

        uint32_t sb = smb + s * GU_STG;
#pragma unroll
        for (int kh = 0; kh < 2; ++kh) {
            uint32_t aF[2][4];
#pragma unroll
            for (int mf = 0; mf < 2; ++mf) {
                uint32_t off = (wm * 32 + mf * 16 + (lane & 15)) * 80 +
                               (kh * 16 + (lane >> 4) * 8) * 2;
                ldsm4(aF[mf], sb + GU_A + off);
            }
            uint32_t bF[8][2];
#pragma unroll
            for (int p = 0; p < 4; ++p) {
                uint32_t off = (kh * 16 + (lane & 15)) * 144 +
                               (p * 16 + (lane >> 4) * 8) * 2;
                ldsm4t(bF[2 * p][0], bF[2 * p][1], bF[2 * p + 1][0], bF[2 * p + 1][1],
                       sb + bOff + off);
            }
#pragma unroll
            for (int mf = 0; mf < 2; ++mf)
#pragma unroll
                for (int nf = 0; nf < 8; ++nf)
                    mma16816(acc[mf][nf], aF[mf], bF[nf]);
        }
    }
    cpa_wait0();
    __syncthreads();

    // epilogue: up warps publish accs in smem, gate warps combine + store fp16
    float* ups = (float*)smem;   // [256][66] = 66 KB < GU_SMEM
    if (isup) {
#pragma unroll
        for (int mf = 0; mf < 2; ++mf)
#pragma unroll
            for (int nf = 0; nf < 8; ++nf)
#pragma unroll
                for (int h = 0; h < 2; ++h) {
                    int row = wm * 32 + mf * 16 + (lane >> 2) + 8 * h;
                    int col = nf * 8 + (lane & 3) * 2;
                    *(float2*)&ups[row * 66 + col] =
                        make_float2(acc[mf][nf][2 * h], acc[mf][nf][2 * h + 1]);
                }
    }
    __syncthreads();
    if (!isup) {
        int goff = g_off[e];
#pragma unroll
        for (int mf = 0; mf < 2; ++mf)
#pragma unroll
            for (int h = 0; h < 2; ++h) {
                int row = wm * 32 + mf * 16 + (lane >> 2) + 8 * h;
                int m = mblk + row;
                if (m < cnt) {
                    size_t hb = (size_t)(goff + m) * IDIM + nblk;
#pragma unroll
                    for (int nf = 0; nf < 8; ++nf) {
                        int col = nf * 8 + (lane & 3) * 2;
                        float g0 = acc[mf][nf][2 * h], g1 = acc[mf][nf][2 * h + 1];
                        float u0 = ups[row * 66 + col], u1 = ups[row * 66 + col + 1];
                        float v0 = g0 / (1.f + expf(-g0)) * u0;
                        float v1 = g1 / (1.f + expf(-g1)) * u1;
                        *(uint32_t*)&g_h[hb + col] = packh2(v0, v1);
                    }
                }
            }
    }
    (void)dummy;
}

// ---------------------------------------------------------------------------
// K4: down fp16. 512 thr, 16 warps (wm 0..7, wn 0..1), warptile m32n64.
//     CTA tile M=256, N=128, BK=32, 3-stage cp.async.
// ---------------------------------------------------------------------------
#define DN_ITERS 32
#define DN_A  0
#define DN_B  20480
#define DN_STG 29184
#define DN_SMEM (3 * DN_STG)

__global__ __launch_bounds__(512, 1)
void down_f16(float* __restrict__ out) {
    int e = blockIdx.z;
    int cnt = g_cnt[e];
    int mblk = blockIdx.y * 256;
    if (mblk >= cnt) return;
    int nblk = blockIdx.x * 128;

    extern __shared__ char smem[];
    uint32_t smb = cvsm(smem);

    const int tid = threadIdx.x;
    const int lane = tid & 31, wid = tid >> 5;
    const int wm = wid >> 1, wn = wid & 1;

    int goff = g_off[e];
    // A loader: 1024 chunks (256 rows x 4), 2 per thread
    int ac1 = tid, ac2 = tid + 512;
    int ar1 = ac1 >> 2, aq1 = ac1 & 3;
    int ar2 = ac2 >> 2, aq2 = ac2 & 3;
    int mr1 = min(mblk + ar1, cnt - 1);
    int mr2 = min(mblk + ar2, cnt - 1);
    const __half* ap1 = g_h + (size_t)(goff + mr1) * IDIM + aq1 * 8;
    const __half* ap2 = g_h + (size_t)(goff + mr2) * IDIM + aq2 * 8;
    const uint32_t sA1 = DN_A + ar1 * 80 + aq1 * 16;
    const uint32_t sA2 = DN_A + ar2 * 80 + aq2 * 16;

    // B loader: 32 rows x 16 chunks = 512, 1 per thread
    size_t we = (size_t)e * IDIM * HDIM;
    int kr1 = (tid >> 4) & 31, q1 = tid & 15;
    const __half* bp1 = g_wd_h + we + (size_t)kr1 * HDIM + nblk + q1 * 8;
    const uint32_t sB1 = DN_B + kr1 * 272 + q1 * 16;

    auto issue = [&](int st, int kb) {
        uint32_t sb = smb + st * DN_STG;
        cpa16(sb + sA1, ap1 + kb);
        cpa16(sb + sA2, ap2 + kb);
        cpa16(sb + sB1, bp1 + (size_t)kb * HDIM);
    };

    float acc[2][8][4] = {};

    issue(0, 0);  cpa_commit();
    issue(1, 32); cpa_commit();

    for (int it = 0; it < DN_ITERS; ++it) {
        int s = it % 3;
        cpa_wait1();
        __syncthreads();
        if (it + 2 < DN_ITERS) issue((it + 2) % 3, (it + 2) * 32);
        cpa_commit();

        uint32_t sb = smb + s * DN_STG;
#pragma unroll
        for (int kh = 0; kh < 2; ++kh) {
            uint32_t aF[2][4];
#pragma unroll
            for (int mf = 0; mf < 2; ++mf) {
                uint32_t off = (wm * 32 + mf * 16 + (lane & 15)) * 80 +
                               (kh * 16 + (lane >> 4) * 8) * 2;
                ldsm4(aF[mf], sb + DN_A + off);
            }
            uint32_t bF[8][2];
#pragma unroll
            for (int p = 0; p < 4; ++p) {
                uint32_t off = (kh * 16 + (lane & 15)) * 272 +
                               (wn * 64 + p * 16 + (lane >> 4) * 8) * 2;
                ldsm4t(bF[2 * p][0], bF[2 * p][1], bF[2 * p + 1][0], bF[2 * p + 1][1],
                       sb + DN_B + off);
            }
#pragma unroll
            for (int mf = 0; mf < 2; ++mf)
#pragma unroll
                for (int nf = 0; nf < 8; ++nf)
                    mma16816(acc[mf][nf], aF[mf], bF[nf]);
        }
    }

    // epilogue: weighted red.v2 scatter
#pragma unroll
    for (int mf = 0; mf < 2; ++mf)
#pragma unroll
        for (int h = 0; h < 2; ++h) {
            int m = mblk + wm * 32 + mf * 16 + (lane >> 2) + 8 * h;
            if (m < cnt) {
                int tok = g_tok[e * TTOK + m];
                float w = g_wt[e * TTOK + m];
                float* orow = out + (size_t)tok * HDIM + nblk + wn * 64;
#pragma unroll
                for (int nf = 0; nf < 8; ++nf) {
                    int col = nf * 8 + (lane & 3) * 2;
                    red2(orow + col, w * acc[mf][nf][2 * h], w * acc[mf][nf][2 * h + 1]);
                }
            }
        }
}

// ---------------------------------------------------------------------------
extern "C" void kernel_launch(void* const* d_in, const int* in_sizes, int n_in,
                              void* d_out, int out_size) {
    const float* x  = (const float*)d_in[0];   // hidden_states [2,1024,2048]
    const float* gw = (const float*)d_in[1];   // gate_w [2048,64]
    const float* wg = (const float*)d_in[2];   // w_gate_proj [64,2048,1024]
    const float* wu = (const float*)d_in[3];   // w_up_proj   [64,2048,1024]
    const float* wd = (const float*)d_in[4];   // w_down_proj [64,1024,2048]
    float* out = (float*)d_out;                // [final | router_logits]

    cudaFuncSetAttribute(gateup_f16, cudaFuncAttributeMaxDynamicSharedMemorySize, GU_SMEM);
    cudaFuncSetAttribute(down_f16,   cudaFuncAttributeMaxDynamicSharedMemorySize, DN_SMEM);

    splitw_kernel<<<dim3(16384, 3), 256>>>((const float4*)wg, (const float4*)wu, (const float4*)wd);
    zero_kernel<<<1024, 256>>>(out);
    router_kernel<<<TTOK, 256>>>(x, gw, out);
    scan_kernel<<<1, 32>>>();

    gateup_f16<<<dim3(16, 8, 64), 512, GU_SMEM>>>(out);
    down_f16<<<dim3(16, 8, 64), 512, DN_SMEM>>>(out);
}

// round 10
// speedup vs baseline: 1.2644x; 1.2644x over previous
#include <cuda_runtime.h>
#include <cuda_fp16.h>
#include <math.h>
#include <stdint.h>

#define TTOK 2048
#define HDIM 2048
#define IDIM 1024
#define ENUM 64
#define KTOP 8

// Scratch (static device globals; no dynamic allocation allowed)
__device__ int   g_cnt[ENUM];
__device__ int   g_off[ENUM];
__device__ int   g_done;
__device__ int   g_tok[ENUM * TTOK];
__device__ float g_wt[ENUM * TTOK];
__device__ __half g_x_h[(size_t)TTOK * HDIM];
__device__ __half g_wg_h[(size_t)ENUM * HDIM * IDIM];
__device__ __half g_wu_h[(size_t)ENUM * HDIM * IDIM];
__device__ __half g_wd_h[(size_t)ENUM * IDIM * HDIM];
__device__ __half g_h[(size_t)TTOK * KTOP * IDIM];

// ---------------------------------------------------------------------------
// helpers
// ---------------------------------------------------------------------------
__device__ __forceinline__ uint32_t cvsm(const void* p) {
    return (uint32_t)__cvta_generic_to_shared(p);
}
__device__ __forceinline__ void ldsm4(uint32_t* r, uint32_t a) {
    asm volatile("ldmatrix.sync.aligned.m8n8.x4.shared.b16 {%0,%1,%2,%3},[%4];"
                 : "=r"(r[0]), "=r"(r[1]), "=r"(r[2]), "=r"(r[3]) : "r"(a));
}
__device__ __forceinline__ void ldsm4t(uint32_t& r0, uint32_t& r1, uint32_t& r2, uint32_t& r3, uint32_t a) {
    asm volatile("ldmatrix.sync.aligned.m8n8.x4.trans.shared.b16 {%0,%1,%2,%3},[%4];"
                 : "=r"(r0), "=r"(r1), "=r"(r2), "=r"(r3) : "r"(a));
}
__device__ __forceinline__ void mma16816(float* c, const uint32_t* a, const uint32_t* b) {
    asm volatile("mma.sync.aligned.m16n8k16.row.col.f32.f16.f16.f32 "
                 "{%0,%1,%2,%3},{%4,%5,%6,%7},{%8,%9},{%0,%1,%2,%3};"
                 : "+f"(c[0]), "+f"(c[1]), "+f"(c[2]), "+f"(c[3])
                 : "r"(a[0]), "r"(a[1]), "r"(a[2]), "r"(a[3]), "r"(b[0]), "r"(b[1]));
}
__device__ __forceinline__ uint32_t packh2(float a, float b) {
    __half2 h = __floats2half2_rn(a, b);
    return *(uint32_t*)&h;
}
__device__ __forceinline__ void cpa16(uint32_t s, const void* g) {
    asm volatile("cp.async.cg.shared.global [%0], [%1], 16;" :: "r"(s), "l"(g));
}
__device__ __forceinline__ void cpa_commit() {
    asm volatile("cp.async.commit_group;");
}
__device__ __forceinline__ void cpa_wait1() {
    asm volatile("cp.async.wait_group 1;");
}
__device__ __forceinline__ void cpa_wait0() {
    asm volatile("cp.async.wait_group 0;");
}
__device__ __forceinline__ void red2(float* p, float a, float b) {
    asm volatile("red.global.add.v2.f32 [%0], {%1,%2};" :: "l"(p), "f"(a), "f"(b) : "memory");
}

// ---------------------------------------------------------------------------
// K0: fused prep — grid.y 0..2: split weight tensors to fp16;
//     grid.y 3: zero the output accumulation region + reset counters.
// ---------------------------------------------------------------------------
__global__ void prep_kernel(const float4* __restrict__ wg,
                            const float4* __restrict__ wu,
                            const float4* __restrict__ wd,
                            float* __restrict__ out) {
    if (blockIdx.y == 3) {
        size_t idx = (size_t)blockIdx.x * blockDim.x + threadIdx.x;
        size_t n4 = (size_t)TTOK * HDIM / 4;
        float4 z = make_float4(0.f, 0.f, 0.f, 0.f);
        for (size_t i = idx; i < n4; i += (size_t)gridDim.x * blockDim.x)
            reinterpret_cast<float4*>(out)[i] = z;
        if (blockIdx.x == 0 && threadIdx.x < ENUM) g_cnt[threadIdx.x] = 0;
        if (blockIdx.x == 0 && threadIdx.x == 0) g_done = 0;
        return;
    }
    const size_t n4 = (size_t)ENUM * HDIM * IDIM / 4;
    const float4* src;
    uint2* dst;
    if (blockIdx.y == 0)      { src = wg; dst = (uint2*)g_wg_h; }
    else if (blockIdx.y == 1) { src = wu; dst = (uint2*)g_wu_h; }
    else                      { src = wd; dst = (uint2*)g_wd_h; }
    size_t idx = (size_t)blockIdx.x * blockDim.x + threadIdx.x;
    size_t stride = (size_t)gridDim.x * blockDim.x;
    for (size_t i = idx; i < n4; i += stride) {
        float4 v = src[i];
        dst[i] = make_uint2(packh2(v.x, v.y), packh2(v.z, v.w));
    }
}

// ---------------------------------------------------------------------------
// K1: router (emits fp16 x copy; last block performs the offset scan)
// ---------------------------------------------------------------------------
__global__ void router_kernel(const float* __restrict__ x,
                              const float* __restrict__ gw,
                              float* __restrict__ out) {
    int t = blockIdx.x;
    __shared__ float xs[HDIM];
    __shared__ float logits[ENUM];
    __shared__ float probs[ENUM];

    const float* xr = x + (size_t)t * HDIM;
    for (int i = threadIdx.x; i < HDIM; i += blockDim.x) xs[i] = xr[i];
    __syncthreads();

    // fp16 copy of this token's row
    for (int i = threadIdx.x; i < HDIM / 2; i += blockDim.x) {
        *(uint32_t*)&g_x_h[(size_t)t * HDIM + 2 * i] = packh2(xs[2 * i], xs[2 * i + 1]);
    }

    int e = threadIdx.x >> 2;
    int part = threadIdx.x & 3;
    float s = 0.f;
    int k0 = part * (HDIM / 4);
    for (int k = k0; k < k0 + HDIM / 4; k++)
        s += xs[k] * gw[(size_t)k * ENUM + e];
    s += __shfl_down_sync(0xffffffffu, s, 2);
    s += __shfl_down_sync(0xffffffffu, s, 1);
    if (part == 0) logits[e] = s;
    __syncthreads();

    if (threadIdx.x < ENUM)
        out[(size_t)TTOK * HDIM + (size_t)t * ENUM + threadIdx.x] = logits[threadIdx.x];

    if (threadIdx.x == 0) {
        float m = -1e30f;
        for (int i = 0; i < ENUM; i++) m = fmaxf(m, logits[i]);
        float sum = 0.f;
        for (int i = 0; i < ENUM; i++) { probs[i] = expf(logits[i] - m); sum += probs[i]; }
        float inv = 1.f / sum;
        for (int k = 0; k < KTOP; k++) {
            int best = 0; float bv = -1.f;
            for (int i = 0; i < ENUM; i++)
                if (probs[i] > bv) { bv = probs[i]; best = i; }
            probs[best] = -2.f;
            int pos = atomicAdd(&g_cnt[best], 1);
            g_tok[best * TTOK + pos] = t;
            g_wt[best * TTOK + pos]  = bv * inv;
        }
        // last router block computes the exclusive scan (fused scan kernel)
        __threadfence();
        int done = atomicAdd(&g_done, 1);
        if (done == TTOK - 1) {
            int acc = 0;
            for (int i = 0; i < ENUM; i++) { g_off[i] = acc; acc += g_cnt[i]; }
            __threadfence();
        }
    }
}

// ---------------------------------------------------------------------------
// K3: gateup fp16. 256 thr, 8 warps: 0-3 gate / 4-7 up, warptile m32n64.
//     CTA tile M=128, N=64 per matrix, BK=32, 3-stage cp.async.  (R8 config)
// ---------------------------------------------------------------------------
#define GU_ITERS 64
#define GU_A  0
#define GU_G  10240
#define GU_U  14848
#define GU_STG 19456
#define GU_SMEM (3 * GU_STG)

__global__ __launch_bounds__(256, 2)
void gateup_f16(float* __restrict__ dummy) {
    int e = blockIdx.z;
    int cnt = g_cnt[e];
    int mblk = blockIdx.y * 128;
    if (mblk >= cnt) return;
    int nblk = blockIdx.x * 64;

    extern __shared__ char smem[];
    uint32_t smb = cvsm(smem);

    const int tid = threadIdx.x;
    const int lane = tid & 31, wid = tid >> 5;
    const int wm = wid & 3;
    const bool isup = wid >= 4;

    // A loader: 512 chunks of 16B (128 rows x 4 chunks), 2 per thread
    int ac1 = tid, ac2 = tid + 256;
    int ar1 = ac1 >> 2, aq1 = ac1 & 3;
    int ar2 = ac2 >> 2, aq2 = ac2 & 3;
    int mr1 = min(mblk + ar1, cnt - 1);
    int mr2 = min(mblk + ar2, cnt - 1);
    const __half* ap1 = g_x_h + (size_t)g_tok[e * TTOK + mr1] * HDIM + aq1 * 8;
    const __half* ap2 = g_x_h + (size_t)g_tok[e * TTOK + mr2] * HDIM + aq2 * 8;
    const uint32_t sA1 = GU_A + ar1 * 80 + aq1 * 16;
    const uint32_t sA2 = GU_A + ar2 * 80 + aq2 * 16;

    // B loader: gate+up, each 32 rows x 8 chunks = 512 total, 2 per thread
    size_t we = (size_t)e * HDIM * IDIM;
    int bc1 = tid, bc2 = tid + 256;
    int t1 = bc1 >> 8, kr1 = (bc1 >> 3) & 31, q1 = bc1 & 7;
    int t2 = bc2 >> 8, kr2 = (bc2 >> 3) & 31, q2 = bc2 & 7;
    const __half* bp1 = (t1 ? g_wu_h : g_wg_h) + we + (size_t)kr1 * IDIM + nblk + q1 * 8;
    const __half* bp2 = (t2 ? g_wu_h : g_wg_h) + we + (size_t)kr2 * IDIM + nblk + q2 * 8;
    const uint32_t sB1 = (t1 ? GU_U : GU_G) + kr1 * 144 + q1 * 16;
    const uint32_t sB2 = (t2 ? GU_U : GU_G) + kr2 * 144 + q2 * 16;

    auto issue = [&](int st, int kb) {
        uint32_t sb = smb + st * GU_STG;
        cpa16(sb + sA1, ap1 + kb);
        cpa16(sb + sA2, ap2 + kb);
        cpa16(sb + sB1, bp1 + (size_t)kb * IDIM);
        cpa16(sb + sB2, bp2 + (size_t)kb * IDIM);
    };

    float acc[2][8][4] = {};
    const uint32_t bOff = isup ? GU_U : GU_G;

    issue(0, 0);  cpa_commit();
    issue(1, 32); cpa_commit();

    for (int it = 0; it < GU_ITERS; ++it) {
        int s = it % 3;
        cpa_wait1();
        __syncthreads();
        if (it + 2 < GU_ITERS) issue((it + 2) % 3, (it + 2) * 32);
        cpa_commit();

        uint32_t sb = smb + s * GU_STG;
#pragma unroll
        for (int kh = 0; kh < 2; ++kh) {
            uint32_t aF[2][4];
#pragma unroll
            for (int mf = 0; mf < 2; ++mf) {
                uint32_t off = (wm * 32 + mf * 16 + (lane & 15)) * 80 +
                               (kh * 16 + (lane >> 4) * 8) * 2;
                ldsm4(aF[mf], sb + GU_A + off);
            }
            uint32_t bF[8][2];
#pragma unroll
            for (int p = 0; p < 4; ++p) {
                uint32_t off = (kh * 16 + (lane & 15)) * 144 +
                               (p * 16 + (lane >> 4) * 8) * 2;
                ldsm4t(bF[2 * p][0], bF[2 * p][1], bF[2 * p + 1][0], bF[2 * p + 1][1],
                       sb + bOff + off);
            }
#pragma unroll
            for (int mf = 0; mf < 2; ++mf)
#pragma unroll
                for (int nf = 0; nf < 8; ++nf)
                    mma16816(acc[mf][nf], aF[mf], bF[nf]);
        }
    }
    cpa_wait0();
    __syncthreads();

    // epilogue: up warps publish accs in smem, gate warps combine + store fp16
    float* ups = (float*)smem;   // [128][66]
    if (isup) {
#pragma unroll
        for (int mf = 0; mf < 2; ++mf)
#pragma unroll
            for (int nf = 0; nf < 8; ++nf)
#pragma unroll
                for (int h = 0; h < 2; ++h) {
                    int row = wm * 32 + mf * 16 + (lane >> 2) + 8 * h;
                    int col = nf * 8 + (lane & 3) * 2;
                    *(float2*)&ups[row * 66 + col] =
                        make_float2(acc[mf][nf][2 * h], acc[mf][nf][2 * h + 1]);
                }
    }
    __syncthreads();
    if (!isup) {
        int goff = g_off[e];
#pragma unroll
        for (int mf = 0; mf < 2; ++mf)
#pragma unroll
            for (int h = 0; h < 2; ++h) {
                int row = wm * 32 + mf * 16 + (lane >> 2) + 8 * h;
                int m = mblk + row;
                if (m < cnt) {
                    size_t hb = (size_t)(goff + m) * IDIM + nblk;
#pragma unroll
                    for (int nf = 0; nf < 8; ++nf) {
                        int col = nf * 8 + (lane & 3) * 2;
                        float g0 = acc[mf][nf][2 * h], g1 = acc[mf][nf][2 * h + 1];
                        float u0 = ups[row * 66 + col], u1 = ups[row * 66 + col + 1];
                        float v0 = g0 / (1.f + expf(-g0)) * u0;
                        float v1 = g1 / (1.f + expf(-g1)) * u1;
                        *(uint32_t*)&g_h[hb + col] = packh2(v0, v1);
                    }
                }
            }
    }
    (void)dummy;
}

// ---------------------------------------------------------------------------
// K4: down fp16. 256 thr, 8 warps (wm 0..3, wn 0..1), warptile m32n64.
//     CTA tile M=128, N=128, BK=32, 3-stage cp.async.  (R8 config)
// ---------------------------------------------------------------------------
#define DN_ITERS 32
#define DN_A  0
#define DN_B  10240
#define DN_STG 18944
#define DN_SMEM (3 * DN_STG)

__global__ __launch_bounds__(256, 2)
void down_f16(float* __restrict__ out) {
    int e = blockIdx.z;
    int cnt = g_cnt[e];
    int mblk = blockIdx.y * 128;
    if (mblk >= cnt) return;
    int nblk = blockIdx.x * 128;

    extern __shared__ char smem[];
    uint32_t smb = cvsm(smem);

    const int tid = threadIdx.x;
    const int lane = tid & 31, wid = tid >> 5;
    const int wm = wid >> 1, wn = wid & 1;

    int goff = g_off[e];
    // A loader: 512 chunks (128 rows x 4), 2 per thread
    int ac1 = tid, ac2 = tid + 256;
    int ar1 = ac1 >> 2, aq1 = ac1 & 3;
    int ar2 = ac2 >> 2, aq2 = ac2 & 3;
    int mr1 = min(mblk + ar1, cnt - 1);
    int mr2 = min(mblk + ar2, cnt - 1);
    const __half* ap1 = g_h + (size_t)(goff + mr1) * IDIM + aq1 * 8;
    const __half* ap2 = g_h + (size_t)(goff + mr2) * IDIM + aq2 * 8;
    const uint32_t sA1 = DN_A + ar1 * 80 + aq1 * 16;
    const uint32_t sA2 = DN_A + ar2 * 80 + aq2 * 16;

    // B loader: 32 rows x 16 chunks = 512, 2 per thread
    size_t we = (size_t)e * IDIM * HDIM;
    int bc1 = tid, bc2 = tid + 256;
    int kr1 = (bc1 >> 4) & 31, q1 = bc1 & 15;
    int kr2 = (bc2 >> 4) & 31, q2 = bc2 & 15;
    const __half* bp1 = g_wd_h + we + (size_t)kr1 * HDIM + nblk + q1 * 8;
    const __half* bp2 = g_wd_h + we + (size_t)kr2 * HDIM + nblk + q2 * 8;
    const uint32_t sB1 = DN_B + kr1 * 272 + q1 * 16;
    const uint32_t sB2 = DN_B + kr2 * 272 + q2 * 16;

    auto issue = [&](int st, int kb) {
        uint32_t sb = smb + st * DN_STG;
        cpa16(sb + sA1, ap1 + kb);
        cpa16(sb + sA2, ap2 + kb);
        cpa16(sb + sB1, bp1 + (size_t)kb * HDIM);
        cpa16(sb + sB2, bp2 + (size_t)kb * HDIM);
    };

    float acc[2][8][4] = {};

    issue(0, 0);  cpa_commit();
    issue(1, 32); cpa_commit();

    for (int it = 0; it < DN_ITERS; ++it) {
        int s = it % 3;
        cpa_wait1();
        __syncthreads();
        if (it + 2 < DN_ITERS) issue((it + 2) % 3, (it + 2) * 32);
        cpa_commit();

        uint32_t sb = smb + s * DN_STG;
#pragma unroll
        for (int kh = 0; kh < 2; ++kh) {
            uint32_t aF[2][4];
#pragma unroll
            for (int mf = 0; mf < 2; ++mf) {
                uint32_t off = (wm * 32 + mf * 16 + (lane & 15)) * 80 +
                               (kh * 16 + (lane >> 4) * 8) * 2;
                ldsm4(aF[mf], sb + DN_A + off);
            }
            uint32_t bF[8][2];
#pragma unroll
            for (int p = 0; p < 4; ++p) {
                uint32_t off = (kh * 16 + (lane & 15)) * 272 +
                               (wn * 64 + p * 16 + (lane >> 4) * 8) * 2;
                ldsm4t(bF[2 * p][0], bF[2 * p][1], bF[2 * p + 1][0], bF[2 * p + 1][1],
                       sb + DN_B + off);
            }
#pragma unroll
            for (int mf = 0; mf < 2; ++mf)
#pragma unroll
                for (int nf = 0; nf < 8; ++nf)
                    mma16816(acc[mf][nf], aF[mf], bF[nf]);
        }
    }

    // epilogue: weighted red.v2 scatter
#pragma unroll
    for (int mf = 0; mf < 2; ++mf)
#pragma unroll
        for (int h = 0; h < 2; ++h) {
            int m = mblk + wm * 32 + mf * 16 + (lane >> 2) + 8 * h;
            if (m < cnt) {
                int tok = g_tok[e * TTOK + m];
                float w = g_wt[e * TTOK + m];
                float* orow = out + (size_t)tok * HDIM + nblk + wn * 64;
#pragma unroll
                for (int nf = 0; nf < 8; ++nf) {
                    int col = nf * 8 + (lane & 3) * 2;
                    red2(orow + col, w * acc[mf][nf][2 * h], w * acc[mf][nf][2 * h + 1]);
                }
            }
        }
}

// ---------------------------------------------------------------------------
extern "C" void kernel_launch(void* const* d_in, const int* in_sizes, int n_in,
                              void* d_out, int out_size) {
    const float* x  = (const float*)d_in[0];   // hidden_states [2,1024,2048]
    const float* gw = (const float*)d_in[1];   // gate_w [2048,64]
    const float* wg = (const float*)d_in[2];   // w_gate_proj [64,2048,1024]
    const float* wu = (const float*)d_in[3];   // w_up_proj   [64,2048,1024]
    const float* wd = (const float*)d_in[4];   // w_down_proj [64,1024,2048]
    float* out = (float*)d_out;                // [final | router_logits]

    cudaFuncSetAttribute(gateup_f16, cudaFuncAttributeMaxDynamicSharedMemorySize, GU_SMEM);
    cudaFuncSetAttribute(down_f16,   cudaFuncAttributeMaxDynamicSharedMemorySize, DN_SMEM);

    prep_kernel<<<dim3(16384, 4), 256>>>((const float4*)wg, (const float4*)wu,
                                         (const float4*)wd, out);
    router_kernel<<<TTOK, 256>>>(x, gw, out);

    gateup_f16<<<dim3(16, 16, 64), 256, GU_SMEM>>>(out);
    down_f16<<<dim3(16, 16, 64), 256, DN_SMEM>>>(out);
}